// round 2
// baseline (speedup 1.0000x reference)
#include <cuda_runtime.h>
#include <cstdint>

// Problem constants (fixed by the dataset)
#define TOK    65536      // B * H * W = 16 * 64 * 64
#define CD     512
#define QKVD   1536
#define NHEAD  16
#define HDIM   32
#define WSZ    8
#define NWIN   1024       // B * 64 windows
#define NTOKW  64         // tokens per window

// Scratch (alloc-free rule: __device__ globals)
__device__ float g_qkv[(size_t)TOK * QKVD];    // 384 MiB
__device__ float g_att[(size_t)TOK * CD];      // 128 MiB
__device__ float g_bias[NHEAD * 64 * 64];      // 256 KiB expanded rel-pos bias

// ---------------------------------------------------------------------------
// Expand bias_table[rel_index] -> g_bias[head][n][m]
// ---------------------------------------------------------------------------
__global__ void bias_expand_kernel(const float* __restrict__ bt,
                                   const int* __restrict__ ri) {
    int idx = blockIdx.x * 256 + threadIdx.x;      // 65536 total
    int h  = idx >> 12;
    int nm = idx & 4095;
    g_bias[idx] = bt[ri[nm] * NHEAD + h];
}

// ---------------------------------------------------------------------------
// GEMM: C[M,N] = A[M,K] @ B[N,K]^T + bias[N]   (both operands K-contiguous)
// Tile 128x64x32, 256 threads, 8x4 micro-tile per thread.
// ---------------------------------------------------------------------------
__global__ __launch_bounds__(256) void gemm_tn_kernel(
    const float* __restrict__ A,
    const float* __restrict__ B,
    const float* __restrict__ bias,
    float* __restrict__ C,
    int M, int N, int K)
{
    __shared__ float As[32][132];   // transposed A tile, padded (16B-aligned rows)
    __shared__ float Bs[32][68];    // transposed B tile, padded

    int tid = threadIdx.x;
    int tx = tid & 15;
    int ty = tid >> 4;
    int m0 = blockIdx.y * 128;
    int n0 = blockIdx.x * 64;

    int lrA = tid >> 1;            // 128 rows, 2 threads/row
    int lcA = (tid & 1) * 16;      // 16 k-values each
    int lrB = tid >> 2;            // 64 rows, 4 threads/row
    int lcB = (tid & 3) * 8;       // 8 k-values each

    const float* Ap = A + (size_t)(m0 + lrA) * K + lcA;
    const float* Bp = B + (size_t)(n0 + lrB) * K + lcB;

    float4 ar[4];
    float4 br[2];
    ar[0] = *(const float4*)(Ap + 0);
    ar[1] = *(const float4*)(Ap + 4);
    ar[2] = *(const float4*)(Ap + 8);
    ar[3] = *(const float4*)(Ap + 12);
    br[0] = *(const float4*)(Bp + 0);
    br[1] = *(const float4*)(Bp + 4);

    float acc[8][4];
#pragma unroll
    for (int i = 0; i < 8; i++)
#pragma unroll
        for (int j = 0; j < 4; j++) acc[i][j] = 0.f;

    int ntiles = K >> 5;
    for (int t = 0; t < ntiles; t++) {
        __syncthreads();
#pragma unroll
        for (int q = 0; q < 4; q++) {
            float4 v = ar[q];
            As[lcA + q * 4 + 0][lrA] = v.x;
            As[lcA + q * 4 + 1][lrA] = v.y;
            As[lcA + q * 4 + 2][lrA] = v.z;
            As[lcA + q * 4 + 3][lrA] = v.w;
        }
#pragma unroll
        for (int q = 0; q < 2; q++) {
            float4 v = br[q];
            Bs[lcB + q * 4 + 0][lrB] = v.x;
            Bs[lcB + q * 4 + 1][lrB] = v.y;
            Bs[lcB + q * 4 + 2][lrB] = v.z;
            Bs[lcB + q * 4 + 3][lrB] = v.w;
        }
        __syncthreads();

        if (t + 1 < ntiles) {
            int k0 = (t + 1) << 5;
            ar[0] = *(const float4*)(Ap + k0 + 0);
            ar[1] = *(const float4*)(Ap + k0 + 4);
            ar[2] = *(const float4*)(Ap + k0 + 8);
            ar[3] = *(const float4*)(Ap + k0 + 12);
            br[0] = *(const float4*)(Bp + k0 + 0);
            br[1] = *(const float4*)(Bp + k0 + 4);
        }

#pragma unroll
        for (int kk = 0; kk < 32; kk++) {
            float4 a0 = *(const float4*)&As[kk][ty * 8];
            float4 a1 = *(const float4*)&As[kk][ty * 8 + 4];
            float4 bv = *(const float4*)&Bs[kk][tx * 4];
            float av[8] = {a0.x, a0.y, a0.z, a0.w, a1.x, a1.y, a1.z, a1.w};
            float bb[4] = {bv.x, bv.y, bv.z, bv.w};
#pragma unroll
            for (int i = 0; i < 8; i++)
#pragma unroll
                for (int j = 0; j < 4; j++)
                    acc[i][j] += av[i] * bb[j];
        }
    }

    float4 bz = *(const float4*)&bias[n0 + tx * 4];
#pragma unroll
    for (int i = 0; i < 8; i++) {
        float4 o;
        o.x = acc[i][0] + bz.x;
        o.y = acc[i][1] + bz.y;
        o.z = acc[i][2] + bz.z;
        o.w = acc[i][3] + bz.w;
        *(float4*)&C[(size_t)(m0 + ty * 8 + i) * N + n0 + tx * 4] = o;
    }
}

// ---------------------------------------------------------------------------
// Attention: one block per (window, head). 128 threads.
// Gathers q/k/v via the shifted token index, computes masked+biased softmax
// attention over 64 tokens, writes back through the same gather index
// (reverse shift/window-reverse cancel exactly).
// ---------------------------------------------------------------------------
__global__ __launch_bounds__(128) void attn_kernel() {
    __shared__ float Q[64][32];
    __shared__ float Ks[64][32];
    __shared__ float V[64][32];
    __shared__ float P[64][65];    // padded: PV reads P[n][m] across 16 n's
    __shared__ int   tok[64];
    __shared__ int   rg[64];

    int tid  = threadIdx.x;
    int win  = blockIdx.x;         // 0..1023
    int head = blockIdx.y;         // 0..15
    int b  = win >> 6;
    int wi = win & 63;
    int wy = wi >> 3;
    int wx = wi & 7;

    if (tid < 64) {
        int r = tid >> 3, c = tid & 7;
        int hs = wy * WSZ + r;     // shifted-image coord (also mask coord)
        int ws = wx * WSZ + c;
        int h = (hs + 4) & 63;     // original coord (roll by -4 inverse)
        int w = (ws + 4) & 63;
        tok[tid] = b * 4096 + h * 64 + w;
        int rh = hs < 56 ? 0 : (hs < 60 ? 1 : 2);
        int rw = ws < 56 ? 0 : (ws < 60 ? 1 : 2);
        rg[tid] = rh * 3 + rw;
    }
    __syncthreads();

    // Load q/k/v for this head: thread pair per token, 16 dims each.
    {
        int i  = tid >> 1;
        int d0 = (tid & 1) * 16;
        const float* base = g_qkv + (size_t)tok[i] * QKVD + head * HDIM + d0;
#pragma unroll
        for (int j = 0; j < 16; j += 4) {
            *(float4*)&Q[i][d0 + j]  = *(const float4*)(base + j);
            *(float4*)&Ks[i][d0 + j] = *(const float4*)(base + 512 + j);
            *(float4*)&V[i][d0 + j]  = *(const float4*)(base + 1024 + j);
        }
    }
    __syncthreads();

    const int n  = tid >> 1;          // row (query token)
    const int mh = (tid & 1) * 32;    // half of key range
    const float scale = 0.176776695296636893f;  // 32^-0.5

    float qr[32];
#pragma unroll
    for (int d = 0; d < 32; d++) qr[d] = Q[n][d];

    const int rn = rg[n];
    const float* bb = g_bias + ((size_t)head << 12) + n * 64 + mh;

    float s[32];
#pragma unroll 4
    for (int m = 0; m < 32; m++) {
        float a = 0.f;
#pragma unroll
        for (int d = 0; d < 32; d++) a += qr[d] * Ks[mh + m][d];
        s[m] = a * scale + bb[m] + (rg[mh + m] == rn ? 0.f : -100.f);
    }

    // softmax over 64 (two threads per row)
    float mx = -1e30f;
#pragma unroll
    for (int m = 0; m < 32; m++) mx = fmaxf(mx, s[m]);
    mx = fmaxf(mx, __shfl_xor_sync(0xffffffffu, mx, 1));
    float sum = 0.f;
#pragma unroll
    for (int m = 0; m < 32; m++) { s[m] = __expf(s[m] - mx); sum += s[m]; }
    sum += __shfl_xor_sync(0xffffffffu, sum, 1);
    float inv = 1.f / sum;
#pragma unroll
    for (int m = 0; m < 32; m++) P[n][mh + m] = s[m] * inv;
    __syncthreads();

    // out[n, d0:d0+16] = sum_m P[n][m] * V[m][:]
    const int d0 = (tid & 1) * 16;
    float acc[16];
#pragma unroll
    for (int dd = 0; dd < 16; dd++) acc[dd] = 0.f;
#pragma unroll 4
    for (int m = 0; m < 64; m++) {
        float p = P[n][m];
#pragma unroll
        for (int dd = 0; dd < 16; dd++) acc[dd] += p * V[m][d0 + dd];
    }

    float* op = g_att + (size_t)tok[n] * CD + head * HDIM + d0;
#pragma unroll
    for (int dd = 0; dd < 16; dd += 4) {
        float4 o = {acc[dd], acc[dd + 1], acc[dd + 2], acc[dd + 3]};
        *(float4*)(op + dd) = o;
    }
}

// ---------------------------------------------------------------------------
extern "C" void kernel_launch(void* const* d_in, const int* in_sizes, int n_in,
                              void* d_out, int out_size) {
    const float* query      = (const float*)d_in[0];
    const float* qkv_w      = (const float*)d_in[1];
    const float* qkv_b      = (const float*)d_in[2];
    const float* proj_w     = (const float*)d_in[3];
    const float* proj_b     = (const float*)d_in[4];
    const float* bias_table = (const float*)d_in[5];
    const int*   rel_index  = (const int*)d_in[6];
    float* out = (float*)d_out;

    float* qkv_ptr;
    float* att_ptr;
    cudaGetSymbolAddress((void**)&qkv_ptr, g_qkv);
    cudaGetSymbolAddress((void**)&att_ptr, g_att);

    // 1. expand relative-position bias to [NH,64,64]
    bias_expand_kernel<<<256, 256>>>(bias_table, rel_index);

    // 2. QKV projection over unpermuted tokens: [65536,512]@[1536,512]^T
    gemm_tn_kernel<<<dim3(QKVD / 64, TOK / 128), 256>>>(
        query, qkv_w, qkv_b, qkv_ptr, TOK, QKVD, CD);

    // 3. windowed attention (shift handled via gather index)
    attn_kernel<<<dim3(NWIN, NHEAD), 128>>>();

    // 4. output projection: [65536,512]@[512,512]^T -> d_out
    gemm_tn_kernel<<<dim3(CD / 64, TOK / 128), 256>>>(
        att_ptr, proj_w, proj_b, out, TOK, CD, CD);
}

// round 4
// speedup vs baseline: 1.5090x; 1.5090x over previous
#include <cuda_runtime.h>
#include <cuda_fp16.h>
#include <cstdint>

// Problem constants (fixed by the dataset)
#define TOK    65536      // B * H * W = 16 * 64 * 64
#define CD     512
#define QKVD   1536
#define NHEAD  16
#define HDIM   32
#define WSZ    8
#define NWIN   1024
#define LOSCALE 2048.0f
#define INV_LOSCALE (1.0f/2048.0f)

// ---------------------------------------------------------------------------
// Scratch (__device__ globals; allocation-free rule)
// ---------------------------------------------------------------------------
__device__ float  g_qkv[(size_t)TOK * QKVD];        // qkv projection result (fp32)
__device__ float  g_bias[NHEAD * 64 * 64];          // expanded rel-pos bias
__device__ __half g_qh[(size_t)TOK * CD];           // query hi
__device__ __half g_ql[(size_t)TOK * CD];           // query lo (x2048)
__device__ __half g_ath[(size_t)TOK * CD];          // attn out hi
__device__ __half g_atl[(size_t)TOK * CD];          // attn out lo (x2048)
__device__ __half g_wqh[(size_t)QKVD * CD];
__device__ __half g_wql[(size_t)QKVD * CD];
__device__ __half g_wph[(size_t)CD * CD];
__device__ __half g_wpl[(size_t)CD * CD];

// ---------------------------------------------------------------------------
// helpers
// ---------------------------------------------------------------------------
__device__ __forceinline__ uint32_t smem_u32(const void* p) {
    uint32_t a;
    asm("{ .reg .u64 t; cvta.to.shared.u64 t, %1; cvt.u32.u64 %0, t; }"
        : "=r"(a) : "l"(p));
    return a;
}

#define CP_ASYNC16(saddr, gptr) \
    asm volatile("cp.async.cg.shared.global [%0], [%1], 16;" \
                 :: "r"(saddr), "l"(gptr))
#define CP_COMMIT() asm volatile("cp.async.commit_group;")

#define LDSM4(r, addr) \
    asm volatile("ldmatrix.sync.aligned.m8n8.x4.shared.b16 {%0,%1,%2,%3}, [%4];" \
        : "=r"((r)[0]), "=r"((r)[1]), "=r"((r)[2]), "=r"((r)[3]) : "r"(addr))

#define MMA16816(d, a, b0, b1) \
    asm volatile("mma.sync.aligned.m16n8k16.row.col.f32.f16.f16.f32 " \
        "{%0,%1,%2,%3}, {%4,%5,%6,%7}, {%8,%9}, {%0,%1,%2,%3};" \
        : "+f"((d)[0]), "+f"((d)[1]), "+f"((d)[2]), "+f"((d)[3]) \
        : "r"((a)[0]), "r"((a)[1]), "r"((a)[2]), "r"((a)[3]), "r"(b0), "r"(b1))

// ---------------------------------------------------------------------------
// Expand bias_table[rel_index] -> g_bias[head][n][m]
// ---------------------------------------------------------------------------
__global__ void bias_expand_kernel(const float* __restrict__ bt,
                                   const int* __restrict__ ri) {
    int idx = blockIdx.x * 256 + threadIdx.x;
    int h  = idx >> 12;
    int nm = idx & 4095;
    g_bias[idx] = bt[ri[nm] * NHEAD + h];
}

// ---------------------------------------------------------------------------
// fp32 -> fp16 hi + (lo * 2048) split, vectorized by 4
// ---------------------------------------------------------------------------
__global__ __launch_bounds__(256) void split_kernel(const float* __restrict__ src,
                                                    __half* __restrict__ hi,
                                                    __half* __restrict__ lo,
                                                    int n4) {
    int idx = blockIdx.x * 256 + threadIdx.x;
    if (idx >= n4) return;
    float4 v = ((const float4*)src)[idx];
    __half h[4], l[4];
    float vv[4] = {v.x, v.y, v.z, v.w};
#pragma unroll
    for (int i = 0; i < 4; i++) {
        h[i] = __float2half_rn(vv[i]);
        l[i] = __float2half_rn((vv[i] - __half2float(h[i])) * LOSCALE);
    }
    ((uint2*)hi)[idx] = *(uint2*)h;
    ((uint2*)lo)[idx] = *(uint2*)l;
}

// ---------------------------------------------------------------------------
// HMMA GEMM: C[M,N] = A[M,K] @ B[N,K]^T + bias[N]
// A,B given as fp16 hi/lo (lo prescaled by 2048).
// CTA tile 128x128, K-chunk 32, cp.async double buffer, mma.sync m16n8k16.
// D0 accumulates Ah*Bh ; D1 accumulates Al*Bh + Ah*Bl (scaled by 2048).
// ---------------------------------------------------------------------------
#define ROWB 80                    // 32 halves + 8 pad  (conflict-free ldmatrix)
#define ARRB (128 * ROWB)          // one operand tile: 10240 B
#define STGB (4 * ARRB)            // Ah,Al,Bh,Bl per stage: 40960 B
#define GEMM_SMEM (2 * STGB)       // 81920 B

__global__ __launch_bounds__(256) void gemm_hmma_kernel(
    const __half* __restrict__ Ah, const __half* __restrict__ Al,
    const __half* __restrict__ Bh, const __half* __restrict__ Bl,
    const float* __restrict__ bias, float* __restrict__ C,
    int M, int N, int K)
{
    extern __shared__ char smem[];
    const uint32_t sbase = smem_u32(smem);

    const int tid  = threadIdx.x;
    const int wid  = tid >> 5;
    const int lane = tid & 31;
    const int m0 = blockIdx.y * 128;
    const int n0 = blockIdx.x * 128;

    // -------- loader mapping: 2 threads/row, 2x16B chunks each --------
    const int lrow = tid >> 1;                 // 0..127
    const int lc0  = (tid & 1) * 2;            // chunk base (16B units)
    const __half* gAh = Ah + (size_t)(m0 + lrow) * K;
    const __half* gAl = Al + (size_t)(m0 + lrow) * K;
    const __half* gBh = Bh + (size_t)(n0 + lrow) * K;
    const __half* gBl = Bl + (size_t)(n0 + lrow) * K;
    const uint32_t srow = sbase + (uint32_t)lrow * ROWB;

    // -------- compute mapping: warp tile 64x32 (2 x 4 warp grid) --------
    const int mw = (wid & 1) * 64;
    const int nw = (wid >> 1) * 32;

    float acc0[4][4][4];
    float acc1[4][4][4];
#pragma unroll
    for (int i = 0; i < 4; i++)
#pragma unroll
        for (int j = 0; j < 4; j++)
#pragma unroll
            for (int q = 0; q < 4; q++) { acc0[i][j][q] = 0.f; acc1[i][j][q] = 0.f; }

    const int ntiles = K >> 5;

    // prologue: stage 0
    {
        const int kc = 0;
#pragma unroll
        for (int c = 0; c < 2; c++) {
            int ch = lc0 + c;
            uint32_t so = srow + ch * 16;
            CP_ASYNC16(so + 0 * ARRB, gAh + kc + ch * 8);
            CP_ASYNC16(so + 1 * ARRB, gAl + kc + ch * 8);
            CP_ASYNC16(so + 2 * ARRB, gBh + kc + ch * 8);
            CP_ASYNC16(so + 3 * ARRB, gBl + kc + ch * 8);
        }
        CP_COMMIT();
    }

    for (int t = 0; t < ntiles; t++) {
        const int s = t & 1;
        if (t + 1 < ntiles) {
            const int kc = (t + 1) * 32;
            const uint32_t sst = srow + (uint32_t)(s ^ 1) * STGB;
#pragma unroll
            for (int c = 0; c < 2; c++) {
                int ch = lc0 + c;
                uint32_t so = sst + ch * 16;
                CP_ASYNC16(so + 0 * ARRB, gAh + kc + ch * 8);
                CP_ASYNC16(so + 1 * ARRB, gAl + kc + ch * 8);
                CP_ASYNC16(so + 2 * ARRB, gBh + kc + ch * 8);
                CP_ASYNC16(so + 3 * ARRB, gBl + kc + ch * 8);
            }
            CP_COMMIT();
            asm volatile("cp.async.wait_group 1;");
        } else {
            asm volatile("cp.async.wait_group 0;");
        }
        __syncthreads();

        const uint32_t st = sbase + (uint32_t)s * STGB;
#pragma unroll
        for (int kk = 0; kk < 2; kk++) {
            const int k16 = kk * 16;
            const uint32_t colb = (uint32_t)(k16 + ((lane >> 4) << 3)) * 2;
            const uint32_t a_off = (uint32_t)(mw + (lane & 15)) * ROWB + colb;
            const uint32_t b_off = (uint32_t)(nw + (lane & 15)) * ROWB + colb;

            uint32_t afh[4][4], afl[4][4];
#pragma unroll
            for (int mt = 0; mt < 4; mt++) {
                LDSM4(afh[mt], st + 0 * ARRB + a_off + mt * 16 * ROWB);
                LDSM4(afl[mt], st + 1 * ARRB + a_off + mt * 16 * ROWB);
            }
            uint32_t bfh[2][4], bfl[2][4];
#pragma unroll
            for (int p = 0; p < 2; p++) {
                LDSM4(bfh[p], st + 2 * ARRB + b_off + p * 16 * ROWB);
                LDSM4(bfl[p], st + 3 * ARRB + b_off + p * 16 * ROWB);
            }

#pragma unroll
            for (int mt = 0; mt < 4; mt++) {
#pragma unroll
                for (int nt = 0; nt < 4; nt++) {
                    const int p = nt >> 1, q = nt & 1;
                    MMA16816(acc0[mt][nt], afh[mt], bfh[p][q], bfh[p][q + 2]);
                    MMA16816(acc1[mt][nt], afl[mt], bfh[p][q], bfh[p][q + 2]);
                    MMA16816(acc1[mt][nt], afh[mt], bfl[p][q], bfl[p][q + 2]);
                }
            }
        }
        __syncthreads();
    }

    // -------- epilogue --------
    const int er = lane >> 2;
    const int ec = (lane & 3) * 2;
#pragma unroll
    for (int mt = 0; mt < 4; mt++) {
        const int row0 = m0 + mw + mt * 16 + er;
#pragma unroll
        for (int nt = 0; nt < 4; nt++) {
            const int col = n0 + nw + nt * 8 + ec;
            float2 bz = *(const float2*)(bias + col);
            float* p0 = C + (size_t)row0 * N + col;
            float* p1 = p0 + (size_t)8 * N;
            float2 o0, o1;
            o0.x = acc0[mt][nt][0] + acc1[mt][nt][0] * INV_LOSCALE + bz.x;
            o0.y = acc0[mt][nt][1] + acc1[mt][nt][1] * INV_LOSCALE + bz.y;
            o1.x = acc0[mt][nt][2] + acc1[mt][nt][2] * INV_LOSCALE + bz.x;
            o1.y = acc0[mt][nt][3] + acc1[mt][nt][3] * INV_LOSCALE + bz.y;
            *(float2*)p0 = o0;
            *(float2*)p1 = o1;
        }
    }
}

// ---------------------------------------------------------------------------
// Attention: one block per (window, head), 128 threads, 2-row blocking.
// Writes hi/lo fp16 output directly (feeds proj GEMM).
// ---------------------------------------------------------------------------
__global__ __launch_bounds__(128) void attn_kernel(__half* __restrict__ out_hi,
                                                   __half* __restrict__ out_lo) {
    __shared__ float Q[64][32];
    __shared__ float Ks[64][32];
    __shared__ float V[64][32];
    __shared__ float P[64][65];
    __shared__ int   tok[64];
    __shared__ int   rg[64];

    const int tid  = threadIdx.x;
    const int win  = blockIdx.x;
    const int head = blockIdx.y;
    const int b  = win >> 6;
    const int wi = win & 63;
    const int wy = wi >> 3;
    const int wx = wi & 7;

    if (tid < 64) {
        int rr = tid >> 3, cc = tid & 7;
        int hs = wy * WSZ + rr;
        int ws = wx * WSZ + cc;
        int h = (hs + 4) & 63;
        int w = (ws + 4) & 63;
        tok[tid] = b * 4096 + h * 64 + w;
        int rh = hs < 56 ? 0 : (hs < 60 ? 1 : 2);
        int rw = ws < 56 ? 0 : (ws < 60 ? 1 : 2);
        rg[tid] = rh * 3 + rw;
    }
    __syncthreads();

    {
        int i  = tid >> 1;
        int d0 = (tid & 1) * 16;
        const float* base = g_qkv + (size_t)tok[i] * QKVD + head * HDIM + d0;
#pragma unroll
        for (int j = 0; j < 16; j += 4) {
            *(float4*)&Q[i][d0 + j]  = *(const float4*)(base + j);
            *(float4*)&Ks[i][d0 + j] = *(const float4*)(base + 512 + j);
            *(float4*)&V[i][d0 + j]  = *(const float4*)(base + 1024 + j);
        }
    }
    __syncthreads();

    const int r    = tid >> 2;        // row pair 0..31
    const int seg  = tid & 3;         // 16-wide m segment / 8-wide d segment
    const int na   = 2 * r, nb = 2 * r + 1;
    const int mb0  = seg * 16;
    const float scale = 0.176776695296636893f;

    float qa[32], qb[32];
#pragma unroll
    for (int d = 0; d < 32; d += 4) {
        float4 va = *(const float4*)&Q[na][d];
        float4 vb = *(const float4*)&Q[nb][d];
        qa[d] = va.x; qa[d+1] = va.y; qa[d+2] = va.z; qa[d+3] = va.w;
        qb[d] = vb.x; qb[d+1] = vb.y; qb[d+2] = vb.z; qb[d+3] = vb.w;
    }

    const int rna = rg[na], rnb = rg[nb];
    const float* bba = g_bias + ((size_t)head << 12) + na * 64 + mb0;
    const float* bbb = g_bias + ((size_t)head << 12) + nb * 64 + mb0;

    float sa[16], sb[16];
#pragma unroll 2
    for (int j = 0; j < 16; j++) {
        int m = mb0 + j;
        float a0 = 0.f, a1 = 0.f;
#pragma unroll
        for (int d = 0; d < 32; d += 4) {
            float4 kv = *(const float4*)&Ks[m][d];
            a0 += qa[d] * kv.x + qa[d+1] * kv.y + qa[d+2] * kv.z + qa[d+3] * kv.w;
            a1 += qb[d] * kv.x + qb[d+1] * kv.y + qb[d+2] * kv.z + qb[d+3] * kv.w;
        }
        int mg = rg[m];
        sa[j] = a0 * scale + bba[j] + (mg == rna ? 0.f : -100.f);
        sb[j] = a1 * scale + bbb[j] + (mg == rnb ? 0.f : -100.f);
    }

    // softmax over 64 keys: 4 threads per row
    float mxa = -1e30f, mxb = -1e30f;
#pragma unroll
    for (int j = 0; j < 16; j++) { mxa = fmaxf(mxa, sa[j]); mxb = fmaxf(mxb, sb[j]); }
    mxa = fmaxf(mxa, __shfl_xor_sync(0xffffffffu, mxa, 1));
    mxa = fmaxf(mxa, __shfl_xor_sync(0xffffffffu, mxa, 2));
    mxb = fmaxf(mxb, __shfl_xor_sync(0xffffffffu, mxb, 1));
    mxb = fmaxf(mxb, __shfl_xor_sync(0xffffffffu, mxb, 2));
    float sua = 0.f, sub = 0.f;
#pragma unroll
    for (int j = 0; j < 16; j++) {
        sa[j] = __expf(sa[j] - mxa); sua += sa[j];
        sb[j] = __expf(sb[j] - mxb); sub += sb[j];
    }
    sua += __shfl_xor_sync(0xffffffffu, sua, 1);
    sua += __shfl_xor_sync(0xffffffffu, sua, 2);
    sub += __shfl_xor_sync(0xffffffffu, sub, 1);
    sub += __shfl_xor_sync(0xffffffffu, sub, 2);
    float iva = 1.f / sua, ivb = 1.f / sub;
#pragma unroll
    for (int j = 0; j < 16; j++) {
        P[na][mb0 + j] = sa[j] * iva;
        P[nb][mb0 + j] = sb[j] * ivb;
    }
    __syncthreads();

    // PV: rows na,nb ; dims seg*8 .. +8
    const int d0 = seg * 8;
    float aca[8], acb[8];
#pragma unroll
    for (int k = 0; k < 8; k++) { aca[k] = 0.f; acb[k] = 0.f; }
#pragma unroll 4
    for (int m = 0; m < 64; m++) {
        float p0 = P[na][m], p1 = P[nb][m];
        float4 v0 = *(const float4*)&V[m][d0];
        float4 v1 = *(const float4*)&V[m][d0 + 4];
        aca[0] += p0 * v0.x; aca[1] += p0 * v0.y; aca[2] += p0 * v0.z; aca[3] += p0 * v0.w;
        aca[4] += p0 * v1.x; aca[5] += p0 * v1.y; aca[6] += p0 * v1.z; aca[7] += p0 * v1.w;
        acb[0] += p1 * v0.x; acb[1] += p1 * v0.y; acb[2] += p1 * v0.z; acb[3] += p1 * v0.w;
        acb[4] += p1 * v1.x; acb[5] += p1 * v1.y; acb[6] += p1 * v1.z; acb[7] += p1 * v1.w;
    }

#pragma unroll
    for (int rr = 0; rr < 2; rr++) {
        const float* acc = rr ? acb : aca;
        int tk = tok[rr ? nb : na];
        size_t off = (size_t)tk * CD + head * HDIM + d0;
        __half hh[8], ll[8];
#pragma unroll
        for (int k = 0; k < 8; k++) {
            hh[k] = __float2half_rn(acc[k]);
            ll[k] = __float2half_rn((acc[k] - __half2float(hh[k])) * LOSCALE);
        }
        *(uint4*)(out_hi + off) = *(uint4*)hh;
        *(uint4*)(out_lo + off) = *(uint4*)ll;
    }
}

// ---------------------------------------------------------------------------
extern "C" void kernel_launch(void* const* d_in, const int* in_sizes, int n_in,
                              void* d_out, int out_size) {
    const float* query      = (const float*)d_in[0];
    const float* qkv_w      = (const float*)d_in[1];
    const float* qkv_b      = (const float*)d_in[2];
    const float* proj_w     = (const float*)d_in[3];
    const float* proj_b     = (const float*)d_in[4];
    const float* bias_table = (const float*)d_in[5];
    const int*   rel_index  = (const int*)d_in[6];
    float* out = (float*)d_out;

    float *qkv_p;
    __half *qh, *ql, *ath, *atl, *wqh, *wql, *wph, *wpl;
    cudaGetSymbolAddress((void**)&qkv_p, g_qkv);
    cudaGetSymbolAddress((void**)&qh,  g_qh);
    cudaGetSymbolAddress((void**)&ql,  g_ql);
    cudaGetSymbolAddress((void**)&ath, g_ath);
    cudaGetSymbolAddress((void**)&atl, g_atl);
    cudaGetSymbolAddress((void**)&wqh, g_wqh);
    cudaGetSymbolAddress((void**)&wql, g_wql);
    cudaGetSymbolAddress((void**)&wph, g_wph);
    cudaGetSymbolAddress((void**)&wpl, g_wpl);

    cudaFuncSetAttribute(gemm_hmma_kernel,
                         cudaFuncAttributeMaxDynamicSharedMemorySize, GEMM_SMEM);

    // 1. bias expand + precision splits
    bias_expand_kernel<<<256, 256>>>(bias_table, rel_index);
    split_kernel<<<(TOK * CD / 4 + 255) / 256, 256>>>(query, qh, ql, TOK * CD / 4);
    split_kernel<<<(QKVD * CD / 4 + 255) / 256, 256>>>(qkv_w, wqh, wql, QKVD * CD / 4);
    split_kernel<<<(CD * CD / 4 + 255) / 256, 256>>>(proj_w, wph, wpl, CD * CD / 4);

    // 2. QKV projection (HMMA): [65536,512] @ [1536,512]^T -> fp32
    gemm_hmma_kernel<<<dim3(QKVD / 128, TOK / 128), 256, GEMM_SMEM>>>(
        qh, ql, wqh, wql, qkv_b, qkv_p, TOK, QKVD, CD);

    // 3. windowed attention (shift via gather index), writes hi/lo fp16
    attn_kernel<<<dim3(NWIN, NHEAD), 128>>>(ath, atl);

    // 4. output projection (HMMA) -> d_out
    gemm_hmma_kernel<<<dim3(CD / 128, TOK / 128), 256, GEMM_SMEM>>>(
        ath, atl, wph, wpl, proj_b, out, TOK, CD, CD);
}

// round 6
// speedup vs baseline: 1.9762x; 1.3096x over previous
#include <cuda_runtime.h>
#include <cuda_fp16.h>
#include <cstdint>

// Problem constants (fixed by the dataset)
#define TOK    65536      // B * H * W = 16 * 64 * 64
#define CD     512
#define QKVD   1536
#define NHEAD  16
#define HDIM   32
#define WSZ    8
#define NWIN   1024
#define LOSCALE 2048.0f
#define INV_LOSCALE (1.0f/2048.0f)

// ---------------------------------------------------------------------------
// Scratch (__device__ globals; allocation-free rule)
// ---------------------------------------------------------------------------
__device__ float  g_qkv[(size_t)TOK * QKVD];        // qkv projection result (fp32)
__device__ float  g_bias[NHEAD * 64 * 64];          // expanded rel-pos bias
__device__ __half g_qh[(size_t)TOK * CD];           // query hi
__device__ __half g_ql[(size_t)TOK * CD];           // query lo (x2048)
__device__ __half g_ath[(size_t)TOK * CD];          // attn out hi
__device__ __half g_atl[(size_t)TOK * CD];          // attn out lo (x2048)
__device__ __half g_wqh[(size_t)QKVD * CD];         // qkv weights hi
__device__ __half g_wph[(size_t)CD * CD];           // proj weights hi

// ---------------------------------------------------------------------------
// helpers
// ---------------------------------------------------------------------------
__device__ __forceinline__ uint32_t smem_u32(const void* p) {
    uint32_t a;
    asm("{ .reg .u64 t; cvta.to.shared.u64 t, %1; cvt.u32.u64 %0, t; }"
        : "=r"(a) : "l"(p));
    return a;
}

#define CP_ASYNC16(saddr, gptr) \
    asm volatile("cp.async.cg.shared.global [%0], [%1], 16;" \
                 :: "r"(saddr), "l"(gptr))
#define CP_COMMIT() asm volatile("cp.async.commit_group;")
#define CP_WAIT2()  asm volatile("cp.async.wait_group 2;")

#define LDSM4(r, addr) \
    asm volatile("ldmatrix.sync.aligned.m8n8.x4.shared.b16 {%0,%1,%2,%3}, [%4];" \
        : "=r"((r)[0]), "=r"((r)[1]), "=r"((r)[2]), "=r"((r)[3]) : "r"(addr))

#define MMA16816(d, a, b0, b1) \
    asm volatile("mma.sync.aligned.m16n8k16.row.col.f32.f16.f16.f32 " \
        "{%0,%1,%2,%3}, {%4,%5,%6,%7}, {%8,%9}, {%0,%1,%2,%3};" \
        : "+f"((d)[0]), "+f"((d)[1]), "+f"((d)[2]), "+f"((d)[3]) \
        : "r"((a)[0]), "r"((a)[1]), "r"((a)[2]), "r"((a)[3]), "r"(b0), "r"(b1))

// ---------------------------------------------------------------------------
// Expand bias_table[rel_index] -> g_bias[head][n][m]
// ---------------------------------------------------------------------------
__global__ void bias_expand_kernel(const float* __restrict__ bt,
                                   const int* __restrict__ ri) {
    int idx = blockIdx.x * 256 + threadIdx.x;
    int h  = idx >> 12;
    int nm = idx & 4095;
    g_bias[idx] = bt[ri[nm] * NHEAD + h];
}

// ---------------------------------------------------------------------------
// fp32 -> fp16 hi + (lo * 2048) split, vectorized by 4
// ---------------------------------------------------------------------------
__global__ __launch_bounds__(256) void split_kernel(const float* __restrict__ src,
                                                    __half* __restrict__ hi,
                                                    __half* __restrict__ lo,
                                                    int n4) {
    int idx = blockIdx.x * 256 + threadIdx.x;
    if (idx >= n4) return;
    float4 v = ((const float4*)src)[idx];
    __half h[4], l[4];
    float vv[4] = {v.x, v.y, v.z, v.w};
#pragma unroll
    for (int i = 0; i < 4; i++) {
        h[i] = __float2half_rn(vv[i]);
        l[i] = __float2half_rn((vv[i] - __half2float(h[i])) * LOSCALE);
    }
    ((uint2*)hi)[idx] = *(uint2*)h;
    if (lo) ((uint2*)lo)[idx] = *(uint2*)l;
}

// ---------------------------------------------------------------------------
// HMMA GEMM (2-term): C[M,N] = (Ah + Al/2048)[M,K] @ Bh[N,K]^T + bias[N]
// CTA tile 128x128, K-chunk 32, 4-stage cp.async pipeline, 512 threads,
// warp tile 32x32 (4x4 warp grid). D0 = Ah*Bh, D1 = Al*Bh (x2048).
// ---------------------------------------------------------------------------
#define ROWB   80                  // 32 halves (64B) + 16B pad: ldmatrix conflict-free
#define ARRB   (128 * ROWB)        // one operand tile: 10240 B
#define STGB   (3 * ARRB)          // Ah, Al, Bh per stage: 30720 B
#define NSTAGE 4
#define GEMM_SMEM (NSTAGE * STGB)  // 122880 B

__global__ __launch_bounds__(512) void gemm_hmma_kernel(
    const __half* __restrict__ Ah, const __half* __restrict__ Al,
    const __half* __restrict__ Bh,
    const float* __restrict__ bias, float* __restrict__ C,
    int M, int N, int K)
{
    extern __shared__ char smem[];
    const uint32_t sbase = smem_u32(smem);

    const int tid  = threadIdx.x;
    const int wid  = tid >> 5;
    const int lane = tid & 31;
    const int m0 = blockIdx.y * 128;
    const int n0 = blockIdx.x * 128;

    // -------- loader mapping: 4 threads/row, one 16B chunk per array --------
    const int lrow = tid >> 2;                 // 0..127
    const int lc   = tid & 3;                  // 16B chunk in the 64B row
    const __half* gAh = Ah + (size_t)(m0 + lrow) * K + lc * 8;
    const __half* gAl = Al + (size_t)(m0 + lrow) * K + lc * 8;
    const __half* gBh = Bh + (size_t)(n0 + lrow) * K + lc * 8;
    const uint32_t soff = (uint32_t)lrow * ROWB + (uint32_t)lc * 16;

    // -------- compute mapping: warp tile 32x32 (4 x 4 warp grid) --------
    const int mw = (wid & 3) * 32;
    const int nw = (wid >> 2) * 32;

    float acc0[2][4][4];
    float acc1[2][4][4];
#pragma unroll
    for (int i = 0; i < 2; i++)
#pragma unroll
        for (int j = 0; j < 4; j++)
#pragma unroll
            for (int q = 0; q < 4; q++) { acc0[i][j][q] = 0.f; acc1[i][j][q] = 0.f; }

    const int ntiles = K >> 5;                 // 16 for K=512

    // prologue: stages 0..2
#pragma unroll
    for (int t = 0; t < NSTAGE - 1; t++) {
        const uint32_t sb = sbase + (uint32_t)t * STGB + soff;
        const int kc = t * 32;
        CP_ASYNC16(sb + 0 * ARRB, gAh + kc);
        CP_ASYNC16(sb + 1 * ARRB, gAl + kc);
        CP_ASYNC16(sb + 2 * ARRB, gBh + kc);
        CP_COMMIT();
    }

    for (int t = 0; t < ntiles; t++) {
        CP_WAIT2();
        __syncthreads();

        // issue loads for stage t+3 (or an empty group to keep counts exact)
        if (t + NSTAGE - 1 < ntiles) {
            const int tn = t + NSTAGE - 1;
            const uint32_t sb = sbase + (uint32_t)(tn & (NSTAGE - 1)) * STGB + soff;
            const int kc = tn * 32;
            CP_ASYNC16(sb + 0 * ARRB, gAh + kc);
            CP_ASYNC16(sb + 1 * ARRB, gAl + kc);
            CP_ASYNC16(sb + 2 * ARRB, gBh + kc);
        }
        CP_COMMIT();

        const uint32_t st = sbase + (uint32_t)(t & (NSTAGE - 1)) * STGB;
#pragma unroll
        for (int kk = 0; kk < 2; kk++) {
            const uint32_t colb = (uint32_t)kk * 32 + ((lane >> 4) << 4);
            const uint32_t a_off = (uint32_t)(mw + (lane & 15)) * ROWB + colb;
            const uint32_t b_off = (uint32_t)(nw + (lane & 15)) * ROWB + colb;

            uint32_t afh[2][4], afl[2][4], bfh[2][4];
            LDSM4(afh[0], st + 0 * ARRB + a_off);
            LDSM4(afh[1], st + 0 * ARRB + a_off + 16 * ROWB);
            LDSM4(afl[0], st + 1 * ARRB + a_off);
            LDSM4(afl[1], st + 1 * ARRB + a_off + 16 * ROWB);
            LDSM4(bfh[0], st + 2 * ARRB + b_off);
            LDSM4(bfh[1], st + 2 * ARRB + b_off + 16 * ROWB);

#pragma unroll
            for (int mt = 0; mt < 2; mt++) {
#pragma unroll
                for (int nt = 0; nt < 4; nt++) {
                    const int p = nt >> 1, q = nt & 1;
                    MMA16816(acc0[mt][nt], afh[mt], bfh[p][q], bfh[p][q + 2]);
                    MMA16816(acc1[mt][nt], afl[mt], bfh[p][q], bfh[p][q + 2]);
                }
            }
        }
        __syncthreads();
    }

    // -------- epilogue --------
    const int er = lane >> 2;
    const int ec = (lane & 3) * 2;
#pragma unroll
    for (int mt = 0; mt < 2; mt++) {
        const int row0 = m0 + mw + mt * 16 + er;
#pragma unroll
        for (int nt = 0; nt < 4; nt++) {
            const int col = n0 + nw + nt * 8 + ec;
            float2 bz = *(const float2*)(bias + col);
            float* p0 = C + (size_t)row0 * N + col;
            float* p1 = p0 + (size_t)8 * N;
            float2 o0, o1;
            o0.x = acc0[mt][nt][0] + acc1[mt][nt][0] * INV_LOSCALE + bz.x;
            o0.y = acc0[mt][nt][1] + acc1[mt][nt][1] * INV_LOSCALE + bz.y;
            o1.x = acc0[mt][nt][2] + acc1[mt][nt][2] * INV_LOSCALE + bz.x;
            o1.y = acc0[mt][nt][3] + acc1[mt][nt][3] * INV_LOSCALE + bz.y;
            *(float2*)p0 = o0;
            *(float2*)p1 = o1;
        }
    }
}

// ---------------------------------------------------------------------------
// Attention: one block per (window, head), 128 threads, 2-row blocking.
// Writes hi/lo fp16 output directly (feeds proj GEMM).
// ---------------------------------------------------------------------------
__global__ __launch_bounds__(128) void attn_kernel(__half* __restrict__ out_hi,
                                                   __half* __restrict__ out_lo) {
    __shared__ float Q[64][32];
    __shared__ float Ks[64][32];
    __shared__ float V[64][32];
    __shared__ float P[64][65];
    __shared__ int   tok[64];
    __shared__ int   rg[64];

    const int tid  = threadIdx.x;
    const int win  = blockIdx.x;
    const int head = blockIdx.y;
    const int b  = win >> 6;
    const int wi = win & 63;
    const int wy = wi >> 3;
    const int wx = wi & 7;

    if (tid < 64) {
        int rr = tid >> 3, cc = tid & 7;
        int hs = wy * WSZ + rr;
        int ws = wx * WSZ + cc;
        int h = (hs + 4) & 63;
        int w = (ws + 4) & 63;
        tok[tid] = b * 4096 + h * 64 + w;
        int rh = hs < 56 ? 0 : (hs < 60 ? 1 : 2);
        int rw = ws < 56 ? 0 : (ws < 60 ? 1 : 2);
        rg[tid] = rh * 3 + rw;
    }
    __syncthreads();

    {
        int i  = tid >> 1;
        int d0 = (tid & 1) * 16;
        const float* base = g_qkv + (size_t)tok[i] * QKVD + head * HDIM + d0;
#pragma unroll
        for (int j = 0; j < 16; j += 4) {
            *(float4*)&Q[i][d0 + j]  = *(const float4*)(base + j);
            *(float4*)&Ks[i][d0 + j] = *(const float4*)(base + 512 + j);
            *(float4*)&V[i][d0 + j]  = *(const float4*)(base + 1024 + j);
        }
    }
    __syncthreads();

    const int r    = tid >> 2;        // row pair 0..31
    const int seg  = tid & 3;         // 16-wide m segment / 8-wide d segment
    const int na   = 2 * r, nb = 2 * r + 1;
    const int mb0  = seg * 16;
    const float scale = 0.176776695296636893f;

    float qa[32], qb[32];
#pragma unroll
    for (int d = 0; d < 32; d += 4) {
        float4 va = *(const float4*)&Q[na][d];
        float4 vb = *(const float4*)&Q[nb][d];
        qa[d] = va.x; qa[d+1] = va.y; qa[d+2] = va.z; qa[d+3] = va.w;
        qb[d] = vb.x; qb[d+1] = vb.y; qb[d+2] = vb.z; qb[d+3] = vb.w;
    }

    const int rna = rg[na], rnb = rg[nb];
    const float* bba = g_bias + ((size_t)head << 12) + na * 64 + mb0;
    const float* bbb = g_bias + ((size_t)head << 12) + nb * 64 + mb0;

    float sa[16], sb[16];
#pragma unroll 2
    for (int j = 0; j < 16; j++) {
        int m = mb0 + j;
        float a0 = 0.f, a1 = 0.f;
#pragma unroll
        for (int d = 0; d < 32; d += 4) {
            float4 kv = *(const float4*)&Ks[m][d];
            a0 += qa[d] * kv.x + qa[d+1] * kv.y + qa[d+2] * kv.z + qa[d+3] * kv.w;
            a1 += qb[d] * kv.x + qb[d+1] * kv.y + qb[d+2] * kv.z + qb[d+3] * kv.w;
        }
        int mg = rg[m];
        sa[j] = a0 * scale + bba[j] + (mg == rna ? 0.f : -100.f);
        sb[j] = a1 * scale + bbb[j] + (mg == rnb ? 0.f : -100.f);
    }

    // softmax over 64 keys: 4 threads per row
    float mxa = -1e30f, mxb = -1e30f;
#pragma unroll
    for (int j = 0; j < 16; j++) { mxa = fmaxf(mxa, sa[j]); mxb = fmaxf(mxb, sb[j]); }
    mxa = fmaxf(mxa, __shfl_xor_sync(0xffffffffu, mxa, 1));
    mxa = fmaxf(mxa, __shfl_xor_sync(0xffffffffu, mxa, 2));
    mxb = fmaxf(mxb, __shfl_xor_sync(0xffffffffu, mxb, 1));
    mxb = fmaxf(mxb, __shfl_xor_sync(0xffffffffu, mxb, 2));
    float sua = 0.f, sub = 0.f;
#pragma unroll
    for (int j = 0; j < 16; j++) {
        sa[j] = __expf(sa[j] - mxa); sua += sa[j];
        sb[j] = __expf(sb[j] - mxb); sub += sb[j];
    }
    sua += __shfl_xor_sync(0xffffffffu, sua, 1);
    sua += __shfl_xor_sync(0xffffffffu, sua, 2);
    sub += __shfl_xor_sync(0xffffffffu, sub, 1);
    sub += __shfl_xor_sync(0xffffffffu, sub, 2);
    float iva = 1.f / sua, ivb = 1.f / sub;
#pragma unroll
    for (int j = 0; j < 16; j++) {
        P[na][mb0 + j] = sa[j] * iva;
        P[nb][mb0 + j] = sb[j] * ivb;
    }
    __syncthreads();

    // PV: rows na,nb ; dims seg*8 .. +8
    const int d0 = seg * 8;
    float aca[8], acb[8];
#pragma unroll
    for (int k = 0; k < 8; k++) { aca[k] = 0.f; acb[k] = 0.f; }
#pragma unroll 4
    for (int m = 0; m < 64; m++) {
        float p0 = P[na][m], p1 = P[nb][m];
        float4 v0 = *(const float4*)&V[m][d0];
        float4 v1 = *(const float4*)&V[m][d0 + 4];
        aca[0] += p0 * v0.x; aca[1] += p0 * v0.y; aca[2] += p0 * v0.z; aca[3] += p0 * v0.w;
        aca[4] += p0 * v1.x; aca[5] += p0 * v1.y; aca[6] += p0 * v1.z; aca[7] += p0 * v1.w;
        acb[0] += p1 * v0.x; acb[1] += p1 * v0.y; acb[2] += p1 * v0.z; acb[3] += p1 * v0.w;
        acb[4] += p1 * v1.x; acb[5] += p1 * v1.y; acb[6] += p1 * v1.z; acb[7] += p1 * v1.w;
    }

#pragma unroll
    for (int rr = 0; rr < 2; rr++) {
        const float* acc = rr ? acb : aca;
        int tk = tok[rr ? nb : na];
        size_t off = (size_t)tk * CD + head * HDIM + d0;
        __half hh[8], ll[8];
#pragma unroll
        for (int k = 0; k < 8; k++) {
            hh[k] = __float2half_rn(acc[k]);
            ll[k] = __float2half_rn((acc[k] - __half2float(hh[k])) * LOSCALE);
        }
        *(uint4*)(out_hi + off) = *(uint4*)hh;
        *(uint4*)(out_lo + off) = *(uint4*)ll;
    }
}

// ---------------------------------------------------------------------------
extern "C" void kernel_launch(void* const* d_in, const int* in_sizes, int n_in,
                              void* d_out, int out_size) {
    const float* query      = (const float*)d_in[0];
    const float* qkv_w      = (const float*)d_in[1];
    const float* qkv_b      = (const float*)d_in[2];
    const float* proj_w     = (const float*)d_in[3];
    const float* proj_b     = (const float*)d_in[4];
    const float* bias_table = (const float*)d_in[5];
    const int*   rel_index  = (const int*)d_in[6];
    float* out = (float*)d_out;

    float *qkv_p;
    __half *qh, *ql, *ath, *atl, *wqh, *wph;
    cudaGetSymbolAddress((void**)&qkv_p, g_qkv);
    cudaGetSymbolAddress((void**)&qh,  g_qh);
    cudaGetSymbolAddress((void**)&ql,  g_ql);
    cudaGetSymbolAddress((void**)&ath, g_ath);
    cudaGetSymbolAddress((void**)&atl, g_atl);
    cudaGetSymbolAddress((void**)&wqh, g_wqh);
    cudaGetSymbolAddress((void**)&wph, g_wph);

    cudaFuncSetAttribute(gemm_hmma_kernel,
                         cudaFuncAttributeMaxDynamicSharedMemorySize, GEMM_SMEM);

    // 1. bias expand + precision splits
    bias_expand_kernel<<<256, 256>>>(bias_table, rel_index);
    split_kernel<<<(TOK * CD / 4 + 255) / 256, 256>>>(query, qh, ql, TOK * CD / 4);
    split_kernel<<<(QKVD * CD / 4 + 255) / 256, 256>>>(qkv_w, wqh, nullptr, QKVD * CD / 4);
    split_kernel<<<(CD * CD / 4 + 255) / 256, 256>>>(proj_w, wph, nullptr, CD * CD / 4);

    // 2. QKV projection (HMMA 2-term): [65536,512] @ [1536,512]^T -> fp32
    gemm_hmma_kernel<<<dim3(QKVD / 128, TOK / 128), 512, GEMM_SMEM>>>(
        qh, ql, wqh, qkv_b, qkv_p, TOK, QKVD, CD);

    // 3. windowed attention (shift via gather index), writes hi/lo fp16
    attn_kernel<<<dim3(NWIN, NHEAD), 128>>>(ath, atl);

    // 4. output projection (HMMA 2-term) -> d_out
    gemm_hmma_kernel<<<dim3(CD / 128, TOK / 128), 512, GEMM_SMEM>>>(
        ath, atl, wph, proj_b, out, TOK, CD, CD);
}